// round 4
// baseline (speedup 1.0000x reference)
#include <cuda_runtime.h>
#include <math.h>

#define BB 8
#define QQ 2048
#define GG 128
#define CC 512
#define NT 512
#define NWARP (NT/32)

// Transposed cost scratch: [b][g][q], contiguous in q for coalesced row scans.
__device__ float g_costT[BB * GG * QQ];

// ---------------------------------------------------------------------------
// Kernel 1: fused focal-class cost + regression costs.
// NOTE: labels are int32 (JAX x64-disabled demotes jnp.int64 -> int32).
// ---------------------------------------------------------------------------
__global__ void cost_kernel(const float* __restrict__ sem,
                            const float* __restrict__ cen,
                            const float* __restrict__ siz,
                            const float* __restrict__ gio,
                            const int* __restrict__ lab,
                            float* __restrict__ out_cost) {
    int idx = blockIdx.x * blockDim.x + threadIdx.x;
    if (idx >= BB * QQ * GG) return;
    int g  = idx % GG;
    int bq = idx / GG;          // b*QQ + q
    int b  = bq / QQ;
    int q  = bq - b * QQ;

    int l = lab[b * GG + g];

    float x = sem[(long long)bq * CC + l];

    float p   = 1.0f / (1.0f + expf(-x));
    float neg = 0.75f * p * p * (-log1pf(-(p - 1e-8f)));
    float pos = 0.25f * (1.0f - p) * (1.0f - p) * (-logf(p + 1e-8f));
    float cost = 2.0f * (pos - neg) + 5.0f * cen[idx] + siz[idx] - 2.0f * gio[idx];

    out_cost[idx] = cost;
    g_costT[((long long)b * GG + g) * QQ + q] = cost;
}

// ---------------------------------------------------------------------------
// Kernel 2: EXACT replica of the reference's (buggy) e-maxx variant.
// In the reference, minv1/way1 are modified COPIES that are discarded, so the
// effective algorithm per inner step is: argmin of the CURRENT row's reduced
// cost over free columns (tie -> lowest j); update potentials along the
// visited chain; follow occupied columns; assign when a free column is hit
// (way==0 collapses the augment to p[j1]=i). float64 arithmetic like np.
// One CTA per batch.
// ---------------------------------------------------------------------------
__global__ void __launch_bounds__(NT, 1)
lsa_kernel(const int* __restrict__ nactual,
           float* __restrict__ out_inds,
           float* __restrict__ out_mask) {
    int b = blockIdx.x;
    int n = nactual[b];
    if (n > GG) n = GG;
    if (n < 0) n = 0;

    __shared__ double v[QQ + 1];
    __shared__ double u[GG + 1];
    __shared__ int    p[QQ + 1];
    __shared__ unsigned char used[QQ + 1];
    __shared__ int    chain[GG + 8];
    __shared__ double wval[NWARP];
    __shared__ int    widx[NWARP];
    __shared__ int    s_row, s_done, s_clen;

    int tid  = threadIdx.x;
    int lane = tid & 31;
    int warp = tid >> 5;

    for (int j = tid; j <= QQ; j += NT) { v[j] = 0.0; p[j] = 0; }
    for (int j = tid; j <= GG; j += NT) u[j] = 0.0;
    __syncthreads();

    const float* Cb = g_costT + (long long)b * GG * QQ;

    for (int i = 1; i <= n; ++i) {
        // per-row init
        for (int j = tid; j <= QQ; j += NT) used[j] = 0;
        if (tid == 0) {
            used[0] = 1; p[0] = i; chain[0] = 0;
            s_clen = 1; s_row = i; s_done = 0;
        }
        __syncthreads();

        while (true) {
            int    row = s_row;
            double ur  = u[row];
            const float* Crow = Cb + (long long)(row - 1) * QQ;

            // block-parallel argmin over free columns (tie -> lowest j)
            double best = INFINITY;
            int    bidx = 0x7fffffff;
            #pragma unroll
            for (int t = 0; t < QQ / NT; ++t) {
                int j = 1 + tid + t * NT;
                if (!used[j]) {
                    double cur = (double)__ldg(&Crow[j - 1]) - ur - v[j];
                    if (cur < best || (cur == best && j < bidx)) {
                        best = cur; bidx = j;
                    }
                }
            }
            #pragma unroll
            for (int off = 16; off; off >>= 1) {
                double ov = __shfl_xor_sync(0xffffffffu, best, off);
                int    oi = __shfl_xor_sync(0xffffffffu, bidx, off);
                if (ov < best || (ov == best && oi < bidx)) { best = ov; bidx = oi; }
            }
            if (lane == 0) { wval[warp] = best; widx[warp] = bidx; }
            __syncthreads();

            if (tid == 0) {
                double B = wval[0]; int I = widx[0];
                #pragma unroll
                for (int w = 1; w < NWARP; ++w) {
                    double ov = wval[w]; int oi = widx[w];
                    if (ov < B || (ov == B && oi < I)) { B = ov; I = oi; }
                }
                double delta = B;
                int    j1    = I;
                int    cl    = s_clen;
                // potentials along the visited chain (rows distinct, incl. p[0]=i)
                for (int t = 0; t < cl; ++t) {
                    int jc = chain[t];
                    u[p[jc]] += delta;
                    v[jc]    -= delta;
                }
                used[j1]  = 1;
                chain[cl] = j1;
                s_clen    = cl + 1;
                if (p[j1] == 0) { p[j1] = i; s_done = 1; }
                else            { s_row = p[j1]; }
            }
            __syncthreads();
            if (s_done) break;
        }
        __syncthreads();   // protect s_* re-init from stragglers' s_done read
    }

    // emit per-proposal matches
    for (int j = tid + 1; j <= QQ; j += NT) {
        int r = p[j];
        out_inds[b * QQ + (j - 1)] = (r > 0) ? (float)(r - 1) : 0.0f;
        out_mask[b * QQ + (j - 1)] = (r > 0) ? 1.0f : 0.0f;
    }
}

// ---------------------------------------------------------------------------
extern "C" void kernel_launch(void* const* d_in, const int* in_sizes, int n_in,
                              void* d_out, int out_size) {
    const float* sem = (const float*)d_in[0];
    const float* cen = (const float*)d_in[1];
    const float* siz = (const float*)d_in[2];
    const float* gio = (const float*)d_in[3];
    const int*   lab = (const int*)d_in[4];   // int32 (JAX x64 disabled)
    const int*   na  = (const int*)d_in[5];   // int32

    float* out = (float*)d_out;
    const int NI = BB * QQ;              // per_prop_gt_inds / mask
    const int NC = BB * QQ * GG;         // final_cost

    float* out_inds = out;
    float* out_mask = out + NI;
    float* out_cost = out + 2 * NI;
    bool   do_lsa   = true;
    if (out_size == NC) {                // defensive: cost-only layout
        out_cost = out;
        do_lsa   = false;
    }

    cost_kernel<<<(NC + 255) / 256, 256>>>(sem, cen, siz, gio, lab, out_cost);
    if (do_lsa) {
        lsa_kernel<<<BB, NT>>>(na, out_inds, out_mask);
    }
}

// round 5
// speedup vs baseline: 2.7478x; 2.7478x over previous
#include <cuda_runtime.h>
#include <math.h>

#define BB 8
#define QQ 2048
#define GG 128
#define CC 512
#define TOPK 160   // >=129 needed; padded to 5 warp-rounds

// Transposed cost scratch: [b][g][q], contiguous in q (feeds the sort).
__device__ float g_costT[BB * GG * QQ];
// Per (b,row) sorted smallest-TOPK entries, packed (ord32(val)<<32)|col(1-based).
__device__ unsigned long long g_top[BB * GG * TOPK];

// ---------------------------------------------------------------------------
// float<->ordered-uint helpers
// ---------------------------------------------------------------------------
__device__ __forceinline__ unsigned int ord32(float f) {
    unsigned int u = __float_as_uint(f);
    return (u & 0x80000000u) ? ~u : (u | 0x80000000u);
}
__device__ __forceinline__ float unord32(unsigned int o) {
    unsigned int u = (o & 0x80000000u) ? (o ^ 0x80000000u) : ~o;
    return __uint_as_float(u);
}
__device__ __forceinline__ unsigned long long ord64(double d) {
    unsigned long long u = (unsigned long long)__double_as_longlong(d);
    return (u >> 63) ? ~u : (u | 0x8000000000000000ull);
}
__device__ __forceinline__ double unord64(unsigned long long o) {
    unsigned long long u = (o >> 63) ? (o ^ 0x8000000000000000ull) : ~o;
    return __longlong_as_double((long long)u);
}

// ---------------------------------------------------------------------------
// Kernel 1: fused focal-class cost + regression costs (int32 labels).
// ---------------------------------------------------------------------------
__global__ void cost_kernel(const float* __restrict__ sem,
                            const float* __restrict__ cen,
                            const float* __restrict__ siz,
                            const float* __restrict__ gio,
                            const int* __restrict__ lab,
                            float* __restrict__ out_cost) {
    int idx = blockIdx.x * blockDim.x + threadIdx.x;
    if (idx >= BB * QQ * GG) return;
    int g  = idx % GG;
    int bq = idx / GG;          // b*QQ + q
    int b  = bq / QQ;
    int q  = bq - b * QQ;

    int l = lab[b * GG + g];
    float x = sem[(long long)bq * CC + l];

    float p   = 1.0f / (1.0f + expf(-x));
    float neg = 0.75f * p * p * (-log1pf(-(p - 1e-8f)));
    float pos = 0.25f * (1.0f - p) * (1.0f - p) * (-logf(p + 1e-8f));
    float cost = 2.0f * (pos - neg) + 5.0f * cen[idx] + siz[idx] - 2.0f * gio[idx];

    out_cost[idx] = cost;
    g_costT[((long long)b * GG + g) * QQ + q] = cost;
}

// ---------------------------------------------------------------------------
// Kernel 2: per (b,row) full bitonic sort of 2048 packed keys; keep TOPK.
// Ascending by (value, column index) — exactly numpy's argmin tie-break.
// ---------------------------------------------------------------------------
__global__ void __launch_bounds__(512)
sort_kernel() {
    __shared__ unsigned long long s[QQ];
    int tid = threadIdx.x;
    const float* rowp = g_costT + (size_t)blockIdx.x * QQ;

    #pragma unroll
    for (int t = 0; t < QQ / 512; ++t) {
        int j = tid + t * 512;
        s[j] = ((unsigned long long)ord32(rowp[j]) << 32) | (unsigned int)(j + 1);
    }
    __syncthreads();

    for (int k = 2; k <= QQ; k <<= 1) {
        for (int jj = k >> 1; jj > 0; jj >>= 1) {
            #pragma unroll
            for (int t = 0; t < QQ / 512; ++t) {
                int i = tid + t * 512;
                int l = i ^ jj;
                if (l > i) {
                    unsigned long long a = s[i], c = s[l];
                    bool asc = ((i & k) == 0);
                    if (asc ? (a > c) : (a < c)) { s[i] = c; s[l] = a; }
                }
            }
            __syncthreads();
        }
    }
    if (tid < TOPK)
        g_top[(size_t)blockIdx.x * TOPK + tid] = s[tid];
}

// ---------------------------------------------------------------------------
// Kernel 3: one-warp-per-batch replica of the reference's degenerate e-maxx
// loop (way/minv copies discarded => per-step fresh argmin + chain follow).
// Split argmin: probe of pre-sorted row list over unmatched columns (v==0
// there, provably) + 128-wide scan over matched columns from shared cache.
// Potential updates deferred to augmentation via delta prefix sums.
// ---------------------------------------------------------------------------
struct SmemLSA {
    float  Mc[GG * 129];          // Mc[slot*129 + (row-1)], bank-conflict-free
    double v_s[GG];               // v per matched slot
    double u_s[GG + 1];           // u per row (1-based)
    double Dj[GG + 2];            // delta prefix at chain join
    unsigned long long mk;        // argmin value (ordered)
    int    mi;                    // argmin col (tie -> lowest)
    int    chain_slot[GG + 2];
    int    chain_row[GG + 2];
    int    slot_col[GG];
    unsigned char col2slot[QQ + 1];   // 0xFF = unmatched
    unsigned char used_slot[GG];      // on current chain
    unsigned char slot_row[GG];       // matched row (1-based)
};

__global__ void __launch_bounds__(32, 1)
lsa_kernel(const int* __restrict__ nactual,
           const float* __restrict__ cost_bqg,
           float* __restrict__ out_inds,
           float* __restrict__ out_mask) {
    extern __shared__ unsigned char smraw[];
    SmemLSA& S = *reinterpret_cast<SmemLSA*>(smraw);

    int b    = blockIdx.x;
    int lane = threadIdx.x;
    int n = nactual[b];
    if (n > GG) n = GG;
    if (n < 0) n = 0;

    for (int t = lane; t <= GG; t += 32) S.u_s[t] = 0.0;
    for (int t = lane; t <= QQ; t += 32) S.col2slot[t] = 0xFF;
    for (int t = lane; t < GG; t += 32) S.used_slot[t] = 0;
    __syncwarp();

    const unsigned long long* top = g_top + (size_t)b * GG * TOPK;
    const float* costb = cost_bqg + (size_t)b * QQ * GG;
    int mcount = 0;

    for (int i = 1; i <= n; ++i) {
        int cl = 1;
        if (lane == 0) { S.chain_row[0] = i; S.Dj[0] = 0.0; }
        double D = 0.0;
        int row = i;
        int j1;
        __syncwarp();

        while (true) {
            double u_row = S.u_s[row];
            const unsigned long long* trow = top + (size_t)(row - 1) * TOPK;

            // --- probe: first unmatched entry of the row's sorted list ---
            double pkey = INFINITY;
            int    pcol = 0x7fffffff;
            for (int r = 0; r < TOPK / 32; ++r) {
                unsigned long long e = __ldg(&trow[r * 32 + lane]);
                int col = (int)(unsigned int)(e & 0xFFFFFFFFu);
                unsigned m = __ballot_sync(0xffffffffu, S.col2slot[col] == 0xFF);
                if (m) {
                    int f = __ffs(m) - 1;
                    unsigned long long ew = __shfl_sync(0xffffffffu, e, f);
                    pkey = (double)unord32((unsigned int)(ew >> 32)) - u_row;
                    pcol = (int)(unsigned int)(ew & 0xFFFFFFFFu);
                    break;
                }
            }

            // --- matched-column scan (shared cache) ---
            unsigned long long bord = ~0ull;
            int bcol = 0x7fffffff;
            #pragma unroll
            for (int t = 0; t < 4; ++t) {
                int slot = lane + t * 32;
                if (slot < mcount && !S.used_slot[slot]) {
                    double key = ((double)S.Mc[slot * 129 + (row - 1)] - u_row)
                                 - S.v_s[slot];
                    unsigned long long o = ord64(key);
                    int c = S.slot_col[slot];
                    if (o < bord || (o == bord && c < bcol)) { bord = o; bcol = c; }
                }
            }
            if (lane == 0) {
                unsigned long long po = ord64(pkey);
                if (po < bord || (po == bord && pcol < bcol)) { bord = po; bcol = pcol; }
                S.mk = ~0ull;
                S.mi = 0x7fffffff;
            }
            __syncwarp();
            if (bord != ~0ull) atomicMin(&S.mk, bord);
            __syncwarp();
            unsigned long long mk = S.mk;
            if (bord == mk) atomicMin(&S.mi, bcol);
            __syncwarp();

            j1 = S.mi;
            D += unord64(mk);            // warp-uniform

            int slot1 = S.col2slot[j1];
            if (slot1 != 0xFF) {         // chase an occupied column
                if (lane == 0) {
                    S.used_slot[slot1] = 1;
                    S.chain_slot[cl]   = slot1;
                    S.chain_row[cl]    = S.slot_row[slot1];
                    S.Dj[cl]           = D;
                }
                row = S.slot_row[slot1];
                cl++;
                __syncwarp();
            } else break;                // free column: augment
        }
        __syncwarp();

        // fill Mc column for the new match (column-contiguous in cost_bqg)
        {
            float4 src = *(const float4*)(costb + (size_t)(j1 - 1) * GG + lane * 4);
            float* dst = &S.Mc[mcount * 129 + lane * 4];
            dst[0] = src.x; dst[1] = src.y; dst[2] = src.z; dst[3] = src.w;
        }
        // deferred potential updates along the chain (rows/slots distinct)
        for (int t = lane; t < cl; t += 32) {
            double acc = D - S.Dj[t];
            S.u_s[S.chain_row[t]] += acc;
            if (t > 0) {
                int s = S.chain_slot[t];
                S.v_s[s] -= acc;
                S.used_slot[s] = 0;      // reset for next inner loop
            }
        }
        if (lane == 0) {
            S.col2slot[j1]     = (unsigned char)mcount;
            S.slot_row[mcount] = (unsigned char)i;
            S.slot_col[mcount] = j1;
            S.v_s[mcount]      = 0.0;    // terminal column: no v update
        }
        mcount++;
        __syncwarp();
    }

    // emit per-proposal matches
    for (int j = lane; j < QQ; j += 32) {
        unsigned char s = S.col2slot[j + 1];
        float ind = 0.0f, mskv = 0.0f;
        if (s != 0xFF) { ind = (float)(S.slot_row[s] - 1); mskv = 1.0f; }
        out_inds[b * QQ + j] = ind;
        out_mask[b * QQ + j] = mskv;
    }
}

// ---------------------------------------------------------------------------
extern "C" void kernel_launch(void* const* d_in, const int* in_sizes, int n_in,
                              void* d_out, int out_size) {
    const float* sem = (const float*)d_in[0];
    const float* cen = (const float*)d_in[1];
    const float* siz = (const float*)d_in[2];
    const float* gio = (const float*)d_in[3];
    const int*   lab = (const int*)d_in[4];
    const int*   na  = (const int*)d_in[5];

    float* out = (float*)d_out;
    const int NI = BB * QQ;
    const int NC = BB * QQ * GG;

    float* out_inds = out;
    float* out_mask = out + NI;
    float* out_cost = out + 2 * NI;
    bool   do_lsa   = true;
    if (out_size == NC) { out_cost = out; do_lsa = false; }

    cost_kernel<<<(NC + 255) / 256, 256>>>(sem, cen, siz, gio, lab, out_cost);
    if (do_lsa) {
        sort_kernel<<<BB * GG, 512>>>();
        static bool attr_set = false;
        if (!attr_set) {
            cudaFuncSetAttribute(lsa_kernel,
                                 cudaFuncAttributeMaxDynamicSharedMemorySize,
                                 (int)sizeof(SmemLSA));
            attr_set = true;
        }
        lsa_kernel<<<BB, 32, sizeof(SmemLSA)>>>(na, out_cost, out_inds, out_mask);
    }
}